// round 5
// baseline (speedup 1.0000x reference)
#include <cuda_runtime.h>
#include <cuda_bf16.h>
#include <cstdint>
#include <cstddef>

#define BATCH 8
#define SEQ   2048
#define DIM   768
#define MTOT  (BATCH*SEQ)   // 16384

// ---------------- scratch (no dynamic allocation allowed) -------------------
__device__ __nv_bfloat16 g_Q  [(size_t)MTOT*DIM];
__device__ __nv_bfloat16 g_K  [(size_t)MTOT*DIM];
__device__ __nv_bfloat16 g_Wqt[(size_t)DIM*DIM];
__device__ __nv_bfloat16 g_Wkt[(size_t)DIM*DIM];
__device__ float g_num[BATCH*SEQ];
__device__ float g_den[BATCH*SEQ];

// ---------------- helpers ----------------------------------------------------
__device__ __forceinline__ uint32_t smem_u32(const void* p) {
    uint32_t a;
    asm("{ .reg .u64 t; cvta.to.shared.u64 t, %1; cvt.u32.u64 %0, t; }"
        : "=r"(a) : "l"(p));
    return a;
}
__device__ __forceinline__ void ldsm_x4(uint32_t* r, uint32_t addr) {
    asm volatile("ldmatrix.sync.aligned.m8n8.x4.shared.b16 {%0,%1,%2,%3}, [%4];"
                 : "=r"(r[0]), "=r"(r[1]), "=r"(r[2]), "=r"(r[3]) : "r"(addr));
}
__device__ __forceinline__ void mma_bf16(float* c, const uint32_t* a,
                                         uint32_t b0, uint32_t b1) {
    asm volatile(
        "mma.sync.aligned.m16n8k16.row.col.f32.bf16.bf16.f32 "
        "{%0,%1,%2,%3}, {%4,%5,%6,%7}, {%8,%9}, {%0,%1,%2,%3};"
        : "+f"(c[0]), "+f"(c[1]), "+f"(c[2]), "+f"(c[3])
        : "r"(a[0]), "r"(a[1]), "r"(a[2]), "r"(a[3]), "r"(b0), "r"(b1));
}
__device__ __forceinline__ float fast_tanh(float x) {
    float y; asm("tanh.approx.f32 %0, %1;" : "=f"(y) : "f"(x)); return y;
}
#define CP16(dst, src) \
    asm volatile("cp.async.cg.shared.global [%0], [%1], 16;" :: "r"(dst), "l"(src))
#define CP_COMMIT() asm volatile("cp.async.commit_group;" ::: "memory")
#define CP_WAIT(N)  asm volatile("cp.async.wait_group %0;" :: "n"(N) : "memory")

// SMEM tile: 128 rows x 64 bf16 (128B) padded to 144 B/row (conflict-free ldmatrix)
#define SROW2 144
#define TILE2 (128*SROW2)      // 18432 bytes
#define NCH   12               // 768 / 64

// ---------------------------------------------------------------------------
__global__ void transpose_bf16(const float* __restrict__ W, __nv_bfloat16* __restrict__ Wt)
{
    __shared__ float t[32][33];
    int tx = threadIdx.x, ty = threadIdx.y;
    int bk = blockIdx.y * 32, bn = blockIdx.x * 32;
#pragma unroll
    for (int j = 0; j < 4; j++)
        t[ty + j * 8][tx] = W[(size_t)(bk + ty + j * 8) * DIM + bn + tx];
    __syncthreads();
#pragma unroll
    for (int j = 0; j < 4; j++)
        Wt[(size_t)(bn + ty + j * 8) * DIM + bk + tx] = __float2bfloat16(t[tx][ty + j * 8]);
}

__global__ void init_accum(float* __restrict__ n, float* __restrict__ d)
{
    const int i = blockIdx.x * blockDim.x + threadIdx.x;
    n[i] = 0.f; d[i] = 0.f;
}

__global__ void finalize(const float* __restrict__ n, const float* __restrict__ d,
                         float* __restrict__ out)
{
    const int i = blockIdx.x * blockDim.x + threadIdx.x;
    out[i] = n[i] / (d[i] + 1e-7f);
}

// ---------------------------------------------------------------------------
// Phase 1: Out[m,n] = bf16( sum_k X_f32[m,k]*Wt_bf16[n,k] + bias[n] )
// CTA 128x128, K chunks of 64. A: f32 loads -> convert AT LOAD -> uint2 regs
// (16 regs) -> bf16 SMEM (2-stage). B: cp.async 3-stage.
// 8 warps (4m x 2n), warp tile 32x64 (mma m16n8k16).
// SMEM layout: A0,A1 | B0,B1,B2 | bias
// ---------------------------------------------------------------------------
#define P1_SMEM (5*TILE2 + 512)

__global__ void __launch_bounds__(256, 2)
gemm_bias_mma(const float* __restrict__ X, const __nv_bfloat16* __restrict__ Wt,
              const float* __restrict__ bias, __nv_bfloat16* __restrict__ Out)
{
    extern __shared__ __align__(16) char smem[];
    const uint32_t sb = smem_u32(smem);
    const int tid = threadIdx.x, lane = tid & 31, wid = tid >> 5;
    const int wm = wid >> 1, wn = wid & 1;
    const int n0 = blockIdx.x * 128, m0 = blockIdx.y * 128;

    float* bias_s = (float*)(smem + 5*TILE2);
    if (tid < 128) bias_s[tid] = bias[n0 + tid];

    const float* Xg = X + (size_t)m0 * DIM;
    const __nv_bfloat16* Bg = Wt + (size_t)n0 * DIM;

    // A load/store mapping: r = tid>>1 (0..127), h = tid&1 (halves of 64 cols)
    const int ar = tid >> 1, ah = tid & 1;
    // B cp.async mapping: 32 rows/pass, 8 segs of 16B
    const int br = tid >> 3, bsg = tid & 7;

    const uint32_t lane_off = (uint32_t)(lane & 15) * SROW2 + (uint32_t)(lane >> 4) * 16;

    float acc[2][8][4];
#pragma unroll
    for (int i = 0; i < 2; i++)
#pragma unroll
        for (int j = 0; j < 8; j++)
#pragma unroll
            for (int q = 0; q < 4; q++) acc[i][j][q] = 0.f;

    // staged A chunk as converted bf16 (uint2 = 16 regs total)
    uint2 va[8];

    // convert-at-load helper
#define LOADA(dst, koff) do { \
        _Pragma("unroll") \
        for (int _p = 0; _p < 8; _p++) { \
            float4 _v = *(const float4*)(Xg + (size_t)ar * DIM + (koff) + ah * 32 + _p * 4); \
            __nv_bfloat162 _lo = __floats2bfloat162_rn(_v.x, _v.y); \
            __nv_bfloat162 _hi = __floats2bfloat162_rn(_v.z, _v.w); \
            (dst)[_p].x = *(uint32_t*)&_lo; (dst)[_p].y = *(uint32_t*)&_hi; \
        } \
    } while (0)

    // ---- prologue ----
    LOADA(va, 0);
    {
        char* A0 = smem;   // bufA[0]
#pragma unroll
        for (int p = 0; p < 8; p++)
            *(uint2*)(A0 + ar * SROW2 + ah * 64 + p * 8) = va[p];
    }
#pragma unroll
    for (int s = 0; s < 2; s++) {   // issue B0, B1
        const uint32_t dstb = sb + 2*TILE2 + s*TILE2;
#pragma unroll
        for (int p = 0; p < 4; p++) {
            const int r = br + p * 32;
            CP16(dstb + r * SROW2 + bsg * 16,
                 (const char*)(Bg + (size_t)r * DIM + s * 64 + bsg * 8));
        }
        CP_COMMIT();
    }
    LOADA(va, 64);   // A chunk 1 -> regs (already bf16)

    // ---- mainloop ----
    for (int c = 0; c < NCH; c++) {
        if (c < NCH - 1) CP_WAIT(1); else CP_WAIT(0);
        __syncthreads();

        if (c + 2 < NCH) {   // issue B chunk c+2
            const uint32_t dstb = sb + 2*TILE2 + ((c + 2) % 3) * TILE2;
#pragma unroll
            for (int p = 0; p < 4; p++) {
                const int r = br + p * 32;
                CP16(dstb + r * SROW2 + bsg * 16,
                     (const char*)(Bg + (size_t)r * DIM + (c + 2) * 64 + bsg * 8));
            }
            CP_COMMIT();
        }
        if (c + 1 < NCH) {   // store A regs (chunk c+1) -> bufA[(c+1)&1]
            char* An = smem + ((c + 1) & 1) * TILE2;
#pragma unroll
            for (int p = 0; p < 8; p++)
                *(uint2*)(An + ar * SROW2 + ah * 64 + p * 8) = va[p];
        }
        if (c + 2 < NCH) LOADA(va, (c + 2) * 64);   // A chunk c+2 -> regs

        const uint32_t As = sb + (c & 1) * TILE2;
        const uint32_t Bs = sb + 2*TILE2 + (c % 3) * TILE2;
#pragma unroll
        for (int ks = 0; ks < 4; ks++) {
            uint32_t a0[4], a1[4];
            ldsm_x4(a0, As + (uint32_t)(wm * 32)      * SROW2 + ks * 32 + lane_off);
            ldsm_x4(a1, As + (uint32_t)(wm * 32 + 16) * SROW2 + ks * 32 + lane_off);
#pragma unroll
            for (int np = 0; np < 4; np++) {
                uint32_t bm[4];
                ldsm_x4(bm, Bs + (uint32_t)(wn * 64 + np * 16) * SROW2 + ks * 32 + lane_off);
                mma_bf16(acc[0][np*2],   a0, bm[0], bm[2]);
                mma_bf16(acc[0][np*2+1], a0, bm[1], bm[3]);
                mma_bf16(acc[1][np*2],   a1, bm[0], bm[2]);
                mma_bf16(acc[1][np*2+1], a1, bm[1], bm[3]);
            }
        }
    }
#undef LOADA

    // epilogue: + bias, bf16 store
#pragma unroll
    for (int mt = 0; mt < 2; mt++) {
        const int m = m0 + wm * 32 + mt * 16 + (lane >> 2);
#pragma unroll
        for (int nt = 0; nt < 8; nt++) {
            const int nl = wn * 64 + nt * 8 + (lane & 3) * 2;
            const float b0 = bias_s[nl], b1 = bias_s[nl + 1];
            __nv_bfloat162 p0 = __floats2bfloat162_rn(acc[mt][nt][0] + b0, acc[mt][nt][1] + b1);
            __nv_bfloat162 p1 = __floats2bfloat162_rn(acc[mt][nt][2] + b0, acc[mt][nt][3] + b1);
            *(__nv_bfloat162*)(Out + (size_t)m       * DIM + n0 + nl) = p0;
            *(__nv_bfloat162*)(Out + (size_t)(m + 8) * DIM + n0 + nl) = p1;
        }
    }
}

// ---------------------------------------------------------------------------
// Phase 2: per (t-block 128, batch, s-half 1024): 8 s-tiles of 128.
// Flattened 96-chunk cp.async 3-stage pipeline (Q & K per chunk, one group).
// Per tile epilogue: e=exp(tanh(qk)); num[t]+=e*qk; den[t]+=e.
// SMEM layout: Q0,Q1,Q2 | K0,K1,K2 | num(512) den(512)
// ---------------------------------------------------------------------------
#define P2_SMEM (6*TILE2 + 1024)
#define GTOT (8*NCH)   // 96

__global__ void __launch_bounds__(256, 2)
attn_mma(const __nv_bfloat16* __restrict__ Q, const __nv_bfloat16* __restrict__ K,
         float* __restrict__ gnum, float* __restrict__ gden)
{
    extern __shared__ __align__(16) char smem[];
    const uint32_t sb = smem_u32(smem);
    float* num_sh = (float*)(smem + 6*TILE2);
    float* den_sh = num_sh + 128;

    const int tid = threadIdx.x, lane = tid & 31, wid = tid >> 5;
    const int wm = wid >> 1, wn = wid & 1;
    const int t0 = blockIdx.x * 128, b = blockIdx.y, sh = blockIdx.z;

    if (tid < 128) { num_sh[tid] = 0.f; den_sh[tid] = 0.f; }

    const __nv_bfloat16* Kg    = K + ((size_t)b * SEQ + t0) * DIM;
    const __nv_bfloat16* Qbase = Q + ((size_t)b * SEQ + sh * 1024) * DIM;

    const int br = tid >> 3, bsg = tid & 7;
    const uint32_t lane_off = (uint32_t)(lane & 15) * SROW2 + (uint32_t)(lane >> 4) * 16;

    float acc[2][8][4];
#pragma unroll
    for (int i = 0; i < 2; i++)
#pragma unroll
        for (int j = 0; j < 8; j++)
#pragma unroll
            for (int q = 0; q < 4; q++) acc[i][j][q] = 0.f;

    // issue chunk gg (Q tile row block + K chunk) into buffer gg%3
#define ATTN_ISSUE(gg) do { \
        const int _st = (gg) / NCH, _cc = (gg) % NCH, _bf = (gg) % 3; \
        const __nv_bfloat16* _Qp = Qbase + (size_t)(_st * 128) * DIM + _cc * 64; \
        const __nv_bfloat16* _Kp = Kg + _cc * 64; \
        const uint32_t _dq = sb + _bf * TILE2; \
        const uint32_t _dk = sb + 3*TILE2 + _bf * TILE2; \
        _Pragma("unroll") \
        for (int _p = 0; _p < 4; _p++) { \
            const int _r = br + _p * 32; \
            CP16(_dq + _r * SROW2 + bsg * 16, (const char*)(_Qp + (size_t)_r * DIM + bsg * 8)); \
            CP16(_dk + _r * SROW2 + bsg * 16, (const char*)(_Kp + (size_t)_r * DIM + bsg * 8)); \
        } \
        CP_COMMIT(); \
    } while (0)

    ATTN_ISSUE(0);
    ATTN_ISSUE(1);

    for (int g = 0; g < GTOT; g++) {
        if (g < GTOT - 1) CP_WAIT(1); else CP_WAIT(0);
        __syncthreads();
        if (g + 2 < GTOT) ATTN_ISSUE(g + 2);

        const uint32_t As = sb + (g % 3) * TILE2;
        const uint32_t Bs = sb + 3*TILE2 + (g % 3) * TILE2;
#pragma unroll
        for (int ks = 0; ks < 4; ks++) {
            uint32_t a0[4], a1[4];
            ldsm_x4(a0, As + (uint32_t)(wm * 32)      * SROW2 + ks * 32 + lane_off);
            ldsm_x4(a1, As + (uint32_t)(wm * 32 + 16) * SROW2 + ks * 32 + lane_off);
#pragma unroll
            for (int np = 0; np < 4; np++) {
                uint32_t bm[4];
                ldsm_x4(bm, Bs + (uint32_t)(wn * 64 + np * 16) * SROW2 + ks * 32 + lane_off);
                mma_bf16(acc[0][np*2],   a0, bm[0], bm[2]);
                mma_bf16(acc[0][np*2+1], a0, bm[1], bm[3]);
                mma_bf16(acc[1][np*2],   a1, bm[0], bm[2]);
                mma_bf16(acc[1][np*2+1], a1, bm[1], bm[3]);
            }
        }

        if ((g % NCH) == NCH - 1) {
            // s-tile complete: epilogue, reduce over s into num/den per t
#pragma unroll
            for (int nt = 0; nt < 8; nt++) {
                float vn0 = 0.f, vn1 = 0.f, vd0 = 0.f, vd1 = 0.f;
#pragma unroll
                for (int mt = 0; mt < 2; mt++) {
                    const float q0 = acc[mt][nt][0], q1 = acc[mt][nt][1];
                    const float q2 = acc[mt][nt][2], q3 = acc[mt][nt][3];
                    const float e0 = __expf(fast_tanh(q0));
                    const float e1 = __expf(fast_tanh(q1));
                    const float e2 = __expf(fast_tanh(q2));
                    const float e3 = __expf(fast_tanh(q3));
                    vn0 += e0 * q0 + e2 * q2;  vd0 += e0 + e2;
                    vn1 += e1 * q1 + e3 * q3;  vd1 += e1 + e3;
                }
#pragma unroll
                for (int o = 4; o <= 16; o <<= 1) {
                    vn0 += __shfl_xor_sync(0xFFFFFFFFu, vn0, o);
                    vn1 += __shfl_xor_sync(0xFFFFFFFFu, vn1, o);
                    vd0 += __shfl_xor_sync(0xFFFFFFFFu, vd0, o);
                    vd1 += __shfl_xor_sync(0xFFFFFFFFu, vd1, o);
                }
                if (lane < 4) {
                    const int col = wn * 64 + nt * 8 + lane * 2;
                    atomicAdd(&num_sh[col],     vn0);
                    atomicAdd(&num_sh[col + 1], vn1);
                    atomicAdd(&den_sh[col],     vd0);
                    atomicAdd(&den_sh[col + 1], vd1);
                }
            }
#pragma unroll
            for (int i = 0; i < 2; i++)
#pragma unroll
                for (int j = 0; j < 8; j++)
#pragma unroll
                    for (int q = 0; q < 4; q++) acc[i][j][q] = 0.f;
        }
    }
    __syncthreads();
    if (tid < 128) {
        atomicAdd(&gnum[(size_t)b * SEQ + t0 + tid], num_sh[tid]);
        atomicAdd(&gden[(size_t)b * SEQ + t0 + tid], den_sh[tid]);
    }
#undef ATTN_ISSUE
}

// ---------------------------------------------------------------------------
extern "C" void kernel_launch(void* const* d_in, const int* in_sizes, int n_in,
                              void* d_out, int out_size)
{
    const float* x1 = (const float*)d_in[0];
    const float* x2 = (const float*)d_in[1];
    const float* Wq = (const float*)d_in[2];
    const float* bq = (const float*)d_in[3];
    const float* Wk = (const float*)d_in[4];
    const float* bk = (const float*)d_in[5];
    float* out = (float*)d_out;

    __nv_bfloat16 *Qp, *Kp, *Wqt, *Wkt;
    float *gnum, *gden;
    cudaGetSymbolAddress((void**)&Qp,  g_Q);
    cudaGetSymbolAddress((void**)&Kp,  g_K);
    cudaGetSymbolAddress((void**)&Wqt, g_Wqt);
    cudaGetSymbolAddress((void**)&Wkt, g_Wkt);
    cudaGetSymbolAddress((void**)&gnum, g_num);
    cudaGetSymbolAddress((void**)&gden, g_den);

    cudaFuncSetAttribute(gemm_bias_mma, cudaFuncAttributeMaxDynamicSharedMemorySize, P1_SMEM);
    cudaFuncSetAttribute(attn_mma,      cudaFuncAttributeMaxDynamicSharedMemorySize, P2_SMEM);

    init_accum<<<BATCH*SEQ/256, 256>>>(gnum, gden);

    dim3 tgrid(DIM / 32, DIM / 32);
    transpose_bf16<<<tgrid, dim3(32, 8)>>>(Wq, Wqt);
    transpose_bf16<<<tgrid, dim3(32, 8)>>>(Wk, Wkt);

    dim3 ggrid(DIM / 128, MTOT / 128);     // (6, 128)
    gemm_bias_mma<<<ggrid, 256, P1_SMEM>>>(x1, Wqt, bq, Qp);
    gemm_bias_mma<<<ggrid, 256, P1_SMEM>>>(x2, Wkt, bk, Kp);

    dim3 agrid(SEQ / 128, BATCH, 2);       // (16, 8, 2)
    attn_mma<<<agrid, 256, P2_SMEM>>>(Qp, Kp, gnum, gden);

    finalize<<<BATCH*SEQ/256, 256>>>(gnum, gden, out);
}

// round 6
// speedup vs baseline: 1.2117x; 1.2117x over previous
#include <cuda_runtime.h>
#include <cuda_bf16.h>
#include <cstdint>
#include <cstddef>

#define BATCH 8
#define SEQ   2048
#define DIM   768
#define MTOT  (BATCH*SEQ)   // 16384

// ---------------- scratch (no dynamic allocation allowed) -------------------
__device__ __nv_bfloat16 g_X1b[(size_t)MTOT*DIM];
__device__ __nv_bfloat16 g_X2b[(size_t)MTOT*DIM];
__device__ __nv_bfloat16 g_Q  [(size_t)MTOT*DIM];
__device__ __nv_bfloat16 g_K  [(size_t)MTOT*DIM];
__device__ __nv_bfloat16 g_Wqt[(size_t)DIM*DIM];
__device__ __nv_bfloat16 g_Wkt[(size_t)DIM*DIM];
__device__ float g_num[BATCH*SEQ];
__device__ float g_den[BATCH*SEQ];

// ---------------- helpers ----------------------------------------------------
__device__ __forceinline__ uint32_t smem_u32(const void* p) {
    uint32_t a;
    asm("{ .reg .u64 t; cvta.to.shared.u64 t, %1; cvt.u32.u64 %0, t; }"
        : "=r"(a) : "l"(p));
    return a;
}
__device__ __forceinline__ void ldsm_x4(uint32_t* r, uint32_t addr) {
    asm volatile("ldmatrix.sync.aligned.m8n8.x4.shared.b16 {%0,%1,%2,%3}, [%4];"
                 : "=r"(r[0]), "=r"(r[1]), "=r"(r[2]), "=r"(r[3]) : "r"(addr));
}
__device__ __forceinline__ void mma_bf16(float* c, const uint32_t* a,
                                         uint32_t b0, uint32_t b1) {
    asm volatile(
        "mma.sync.aligned.m16n8k16.row.col.f32.bf16.bf16.f32 "
        "{%0,%1,%2,%3}, {%4,%5,%6,%7}, {%8,%9}, {%0,%1,%2,%3};"
        : "+f"(c[0]), "+f"(c[1]), "+f"(c[2]), "+f"(c[3])
        : "r"(a[0]), "r"(a[1]), "r"(a[2]), "r"(a[3]), "r"(b0), "r"(b1));
}
__device__ __forceinline__ float fast_tanh(float x) {
    float y; asm("tanh.approx.f32 %0, %1;" : "=f"(y) : "f"(x)); return y;
}
#define CP16(dst, src) \
    asm volatile("cp.async.cg.shared.global [%0], [%1], 16;" :: "r"(dst), "l"(src))
#define CP_COMMIT() asm volatile("cp.async.commit_group;" ::: "memory")
#define CP_WAIT(N)  asm volatile("cp.async.wait_group %0;" :: "n"(N) : "memory")

// SMEM tile: 128 rows x 64 bf16 (128B) padded to 144 B/row (conflict-free ldmatrix)
#define SROW2 144
#define TILE2 (128*SROW2)      // 18432 bytes
#define NCH   12               // 768 / 64

// Shared 128x128x64 chunk MMA with B-fragment ping-pong prefetch.
// Uses: acc[2][8][4], wm, wn, lane_off from enclosing scope.
#define CHUNK_MMA(AsX, BsX) do { \
    _Pragma("unroll") \
    for (int ks = 0; ks < 4; ks++) { \
        uint32_t a0[4], a1[4], bmA[4], bmB[4]; \
        ldsm_x4(a0,  (AsX) + (uint32_t)(wm * 32)      * SROW2 + ks * 32 + lane_off); \
        ldsm_x4(a1,  (AsX) + (uint32_t)(wm * 32 + 16) * SROW2 + ks * 32 + lane_off); \
        ldsm_x4(bmA, (BsX) + (uint32_t)(wn * 64)      * SROW2 + ks * 32 + lane_off); \
        _Pragma("unroll") \
        for (int np = 0; np < 4; np++) { \
            uint32_t* bc = (np & 1) ? bmB : bmA; \
            uint32_t* bn_ = (np & 1) ? bmA : bmB; \
            if (np < 3) \
                ldsm_x4(bn_, (BsX) + (uint32_t)(wn * 64 + (np + 1) * 16) * SROW2 \
                               + ks * 32 + lane_off); \
            mma_bf16(acc[0][np*2],   a0, bc[0], bc[2]); \
            mma_bf16(acc[0][np*2+1], a0, bc[1], bc[3]); \
            mma_bf16(acc[1][np*2],   a1, bc[0], bc[2]); \
            mma_bf16(acc[1][np*2+1], a1, bc[1], bc[3]); \
        } \
    } \
} while (0)

// ---------------------------------------------------------------------------
// small elementwise kernels
// ---------------------------------------------------------------------------
__global__ void convert_bf16(const float* __restrict__ x, __nv_bfloat16* __restrict__ y)
{
    const size_t i = ((size_t)blockIdx.x * blockDim.x + threadIdx.x) * 8;
    float4 v0 = *(const float4*)(x + i);
    float4 v1 = *(const float4*)(x + i + 4);
    __nv_bfloat162 a = __floats2bfloat162_rn(v0.x, v0.y);
    __nv_bfloat162 b = __floats2bfloat162_rn(v0.z, v0.w);
    __nv_bfloat162 c = __floats2bfloat162_rn(v1.x, v1.y);
    __nv_bfloat162 d = __floats2bfloat162_rn(v1.z, v1.w);
    uint4 st; st.x = *(uint32_t*)&a; st.y = *(uint32_t*)&b;
    st.z = *(uint32_t*)&c; st.w = *(uint32_t*)&d;
    *(uint4*)(y + i) = st;
}

__global__ void transpose_bf16(const float* __restrict__ W, __nv_bfloat16* __restrict__ Wt)
{
    __shared__ float t[32][33];
    int tx = threadIdx.x, ty = threadIdx.y;
    int bk = blockIdx.y * 32, bn = blockIdx.x * 32;
#pragma unroll
    for (int j = 0; j < 4; j++)
        t[ty + j * 8][tx] = W[(size_t)(bk + ty + j * 8) * DIM + bn + tx];
    __syncthreads();
#pragma unroll
    for (int j = 0; j < 4; j++)
        Wt[(size_t)(bn + ty + j * 8) * DIM + bk + tx] = __float2bfloat16(t[tx][ty + j * 8]);
}

__global__ void init_accum(float* __restrict__ n, float* __restrict__ d)
{
    const int i = blockIdx.x * blockDim.x + threadIdx.x;
    n[i] = 0.f; d[i] = 0.f;
}

__global__ void finalize(const float* __restrict__ n, const float* __restrict__ d,
                         float* __restrict__ out)
{
    const int i = blockIdx.x * blockDim.x + threadIdx.x;
    out[i] = n[i] / (d[i] + 1e-7f);
}

// ---------------------------------------------------------------------------
// Phase 1: Out[m,n] = bf16( sum_k A_bf16[m,k]*Wt_bf16[n,k] + bias[n] )
// CTA 128x128, K chunks of 64, cp.async 3-stage for BOTH A and B.
// 8 warps (4m x 2n), warp tile 32x64 (mma m16n8k16).
// SMEM layout: A0,A1,A2 | B0,B1,B2 | bias
// ---------------------------------------------------------------------------
#define P1_SMEM (6*TILE2 + 512)

__global__ void __launch_bounds__(256, 2)
gemm_bias_mma(const __nv_bfloat16* __restrict__ A, const __nv_bfloat16* __restrict__ Bt,
              const float* __restrict__ bias, __nv_bfloat16* __restrict__ Out)
{
    extern __shared__ __align__(16) char smem[];
    const uint32_t sb = smem_u32(smem);
    const int tid = threadIdx.x, lane = tid & 31, wid = tid >> 5;
    const int wm = wid >> 1, wn = wid & 1;
    const int n0 = blockIdx.x * 128, m0 = blockIdx.y * 128;

    float* bias_s = (float*)(smem + 6*TILE2);
    if (tid < 128) bias_s[tid] = bias[n0 + tid];

    const __nv_bfloat16* Ag = A  + (size_t)m0 * DIM;
    const __nv_bfloat16* Bg = Bt + (size_t)n0 * DIM;

    const int br = tid >> 3, bsg = tid & 7;   // 32 rows/pass, 8 segs of 16B
    const uint32_t lane_off = (uint32_t)(lane & 15) * SROW2 + (uint32_t)(lane >> 4) * 16;

    float acc[2][8][4];
#pragma unroll
    for (int i = 0; i < 2; i++)
#pragma unroll
        for (int j = 0; j < 8; j++)
#pragma unroll
            for (int q = 0; q < 4; q++) acc[i][j][q] = 0.f;

#define GEMM_ISSUE(cc) do { \
        const int _bf = (cc) % 3; \
        const uint32_t _da = sb + _bf * TILE2; \
        const uint32_t _db = sb + 3*TILE2 + _bf * TILE2; \
        _Pragma("unroll") \
        for (int _p = 0; _p < 4; _p++) { \
            const int _r = br + _p * 32; \
            CP16(_da + _r * SROW2 + bsg * 16, \
                 (const char*)(Ag + (size_t)_r * DIM + (cc) * 64 + bsg * 8)); \
            CP16(_db + _r * SROW2 + bsg * 16, \
                 (const char*)(Bg + (size_t)_r * DIM + (cc) * 64 + bsg * 8)); \
        } \
        CP_COMMIT(); \
    } while (0)

    GEMM_ISSUE(0);
    GEMM_ISSUE(1);

    for (int c = 0; c < NCH; c++) {
        if (c < NCH - 1) CP_WAIT(1); else CP_WAIT(0);
        __syncthreads();
        if (c + 2 < NCH) GEMM_ISSUE(c + 2);

        const uint32_t As = sb + (c % 3) * TILE2;
        const uint32_t Bs = sb + 3*TILE2 + (c % 3) * TILE2;
        CHUNK_MMA(As, Bs);
    }
#undef GEMM_ISSUE

    // epilogue: + bias, bf16 store
#pragma unroll
    for (int mt = 0; mt < 2; mt++) {
        const int m = m0 + wm * 32 + mt * 16 + (lane >> 2);
#pragma unroll
        for (int nt = 0; nt < 8; nt++) {
            const int nl = wn * 64 + nt * 8 + (lane & 3) * 2;
            const float b0 = bias_s[nl], b1 = bias_s[nl + 1];
            __nv_bfloat162 p0 = __floats2bfloat162_rn(acc[mt][nt][0] + b0, acc[mt][nt][1] + b1);
            __nv_bfloat162 p1 = __floats2bfloat162_rn(acc[mt][nt][2] + b0, acc[mt][nt][3] + b1);
            *(__nv_bfloat162*)(Out + (size_t)m       * DIM + n0 + nl) = p0;
            *(__nv_bfloat162*)(Out + (size_t)(m + 8) * DIM + n0 + nl) = p1;
        }
    }
}

// ---------------------------------------------------------------------------
// Phase 2: per (t-block 128, batch, s-half 1024): 8 s-tiles of 128.
// Flattened 96-chunk cp.async 3-stage pipeline (Q & K per chunk, one group).
// Per tile epilogue: e=exp(tanh(qk)); num[t]+=e*qk; den[t]+=e.
// SMEM layout: Q0,Q1,Q2 | K0,K1,K2 | num(512) den(512)
// ---------------------------------------------------------------------------
#define P2_SMEM (6*TILE2 + 1024)
#define GTOT (8*NCH)   // 96

__global__ void __launch_bounds__(256, 2)
attn_mma(const __nv_bfloat16* __restrict__ Q, const __nv_bfloat16* __restrict__ K,
         float* __restrict__ gnum, float* __restrict__ gden)
{
    extern __shared__ __align__(16) char smem[];
    const uint32_t sb = smem_u32(smem);
    float* num_sh = (float*)(smem + 6*TILE2);
    float* den_sh = num_sh + 128;

    const int tid = threadIdx.x, lane = tid & 31, wid = tid >> 5;
    const int wm = wid >> 1, wn = wid & 1;
    const int t0 = blockIdx.x * 128, b = blockIdx.y, sh = blockIdx.z;

    if (tid < 128) { num_sh[tid] = 0.f; den_sh[tid] = 0.f; }

    const __nv_bfloat16* Kg    = K + ((size_t)b * SEQ + t0) * DIM;
    const __nv_bfloat16* Qbase = Q + ((size_t)b * SEQ + sh * 1024) * DIM;

    const int br = tid >> 3, bsg = tid & 7;
    const uint32_t lane_off = (uint32_t)(lane & 15) * SROW2 + (uint32_t)(lane >> 4) * 16;

    float acc[2][8][4];
#pragma unroll
    for (int i = 0; i < 2; i++)
#pragma unroll
        for (int j = 0; j < 8; j++)
#pragma unroll
            for (int q = 0; q < 4; q++) acc[i][j][q] = 0.f;

#define ATTN_ISSUE(gg) do { \
        const int _st = (gg) / NCH, _cc = (gg) % NCH, _bf = (gg) % 3; \
        const __nv_bfloat16* _Qp = Qbase + (size_t)(_st * 128) * DIM + _cc * 64; \
        const __nv_bfloat16* _Kp = Kg + _cc * 64; \
        const uint32_t _dq = sb + _bf * TILE2; \
        const uint32_t _dk = sb + 3*TILE2 + _bf * TILE2; \
        _Pragma("unroll") \
        for (int _p = 0; _p < 4; _p++) { \
            const int _r = br + _p * 32; \
            CP16(_dq + _r * SROW2 + bsg * 16, (const char*)(_Qp + (size_t)_r * DIM + bsg * 8)); \
            CP16(_dk + _r * SROW2 + bsg * 16, (const char*)(_Kp + (size_t)_r * DIM + bsg * 8)); \
        } \
        CP_COMMIT(); \
    } while (0)

    ATTN_ISSUE(0);
    ATTN_ISSUE(1);

    for (int g = 0; g < GTOT; g++) {
        if (g < GTOT - 1) CP_WAIT(1); else CP_WAIT(0);
        __syncthreads();
        if (g + 2 < GTOT) ATTN_ISSUE(g + 2);

        const uint32_t As = sb + (g % 3) * TILE2;
        const uint32_t Bs = sb + 3*TILE2 + (g % 3) * TILE2;
        CHUNK_MMA(As, Bs);

        if ((g % NCH) == NCH - 1) {
            // s-tile complete: epilogue, reduce over s into num/den per t
#pragma unroll
            for (int nt = 0; nt < 8; nt++) {
                float vn0 = 0.f, vn1 = 0.f, vd0 = 0.f, vd1 = 0.f;
#pragma unroll
                for (int mt = 0; mt < 2; mt++) {
                    const float q0 = acc[mt][nt][0], q1 = acc[mt][nt][1];
                    const float q2 = acc[mt][nt][2], q3 = acc[mt][nt][3];
                    const float e0 = __expf(fast_tanh(q0));
                    const float e1 = __expf(fast_tanh(q1));
                    const float e2 = __expf(fast_tanh(q2));
                    const float e3 = __expf(fast_tanh(q3));
                    vn0 += e0 * q0 + e2 * q2;  vd0 += e0 + e2;
                    vn1 += e1 * q1 + e3 * q3;  vd1 += e1 + e3;
                }
#pragma unroll
                for (int o = 4; o <= 16; o <<= 1) {
                    vn0 += __shfl_xor_sync(0xFFFFFFFFu, vn0, o);
                    vn1 += __shfl_xor_sync(0xFFFFFFFFu, vn1, o);
                    vd0 += __shfl_xor_sync(0xFFFFFFFFu, vd0, o);
                    vd1 += __shfl_xor_sync(0xFFFFFFFFu, vd1, o);
                }
                if (lane < 4) {
                    const int col = wn * 64 + nt * 8 + lane * 2;
                    atomicAdd(&num_sh[col],     vn0);
                    atomicAdd(&num_sh[col + 1], vn1);
                    atomicAdd(&den_sh[col],     vd0);
                    atomicAdd(&den_sh[col + 1], vd1);
                }
            }
#pragma unroll
            for (int i = 0; i < 2; i++)
#pragma unroll
                for (int j = 0; j < 8; j++)
#pragma unroll
                    for (int q = 0; q < 4; q++) acc[i][j][q] = 0.f;
        }
    }
    __syncthreads();
    if (tid < 128) {
        atomicAdd(&gnum[(size_t)b * SEQ + t0 + tid], num_sh[tid]);
        atomicAdd(&gden[(size_t)b * SEQ + t0 + tid], den_sh[tid]);
    }
#undef ATTN_ISSUE
}

// ---------------------------------------------------------------------------
extern "C" void kernel_launch(void* const* d_in, const int* in_sizes, int n_in,
                              void* d_out, int out_size)
{
    const float* x1 = (const float*)d_in[0];
    const float* x2 = (const float*)d_in[1];
    const float* Wq = (const float*)d_in[2];
    const float* bq = (const float*)d_in[3];
    const float* Wk = (const float*)d_in[4];
    const float* bk = (const float*)d_in[5];
    float* out = (float*)d_out;

    __nv_bfloat16 *X1b, *X2b, *Qp, *Kp, *Wqt, *Wkt;
    float *gnum, *gden;
    cudaGetSymbolAddress((void**)&X1b, g_X1b);
    cudaGetSymbolAddress((void**)&X2b, g_X2b);
    cudaGetSymbolAddress((void**)&Qp,  g_Q);
    cudaGetSymbolAddress((void**)&Kp,  g_K);
    cudaGetSymbolAddress((void**)&Wqt, g_Wqt);
    cudaGetSymbolAddress((void**)&Wkt, g_Wkt);
    cudaGetSymbolAddress((void**)&gnum, g_num);
    cudaGetSymbolAddress((void**)&gden, g_den);

    cudaFuncSetAttribute(gemm_bias_mma, cudaFuncAttributeMaxDynamicSharedMemorySize, P1_SMEM);
    cudaFuncSetAttribute(attn_mma,      cudaFuncAttributeMaxDynamicSharedMemorySize, P2_SMEM);

    init_accum<<<BATCH*SEQ/256, 256>>>(gnum, gden);

    const int nconv = (int)(((size_t)MTOT * DIM / 8) / 256);   // 6144 blocks
    convert_bf16<<<nconv, 256>>>(x1, X1b);
    convert_bf16<<<nconv, 256>>>(x2, X2b);

    dim3 tgrid(DIM / 32, DIM / 32);
    transpose_bf16<<<tgrid, dim3(32, 8)>>>(Wq, Wqt);
    transpose_bf16<<<tgrid, dim3(32, 8)>>>(Wk, Wkt);

    dim3 ggrid(DIM / 128, MTOT / 128);     // (6, 128)
    gemm_bias_mma<<<ggrid, 256, P1_SMEM>>>(X1b, Wqt, bq, Qp);
    gemm_bias_mma<<<ggrid, 256, P1_SMEM>>>(X2b, Wkt, bk, Kp);

    dim3 agrid(SEQ / 128, BATCH, 2);       // (16, 8, 2)
    attn_mma<<<agrid, 256, P2_SMEM>>>(Qp, Kp, gnum, gden);

    finalize<<<BATCH*SEQ/256, 256>>>(gnum, gden, out);
}

// round 7
// speedup vs baseline: 1.2778x; 1.0545x over previous
#include <cuda_runtime.h>
#include <cuda_bf16.h>
#include <cstdint>
#include <cstddef>

#define BATCH 8
#define SEQ   2048
#define DIM   768
#define MTOT  (BATCH*SEQ)   // 16384

// ---------------- scratch (no dynamic allocation allowed) -------------------
__device__ __nv_bfloat16 g_X1b[(size_t)MTOT*DIM];
__device__ __nv_bfloat16 g_X2b[(size_t)MTOT*DIM];
__device__ __nv_bfloat16 g_Q  [(size_t)MTOT*DIM];
__device__ __nv_bfloat16 g_K  [(size_t)MTOT*DIM];
__device__ __nv_bfloat16 g_Wqt[(size_t)DIM*DIM];
__device__ __nv_bfloat16 g_Wkt[(size_t)DIM*DIM];
__device__ float g_num[2][BATCH*SEQ];
__device__ float g_den[2][BATCH*SEQ];

// ---------------- helpers ----------------------------------------------------
__device__ __forceinline__ uint32_t smem_u32(const void* p) {
    uint32_t a;
    asm("{ .reg .u64 t; cvta.to.shared.u64 t, %1; cvt.u32.u64 %0, t; }"
        : "=r"(a) : "l"(p));
    return a;
}
__device__ __forceinline__ void ldsm_x4(uint32_t* r, uint32_t addr) {
    asm volatile("ldmatrix.sync.aligned.m8n8.x4.shared.b16 {%0,%1,%2,%3}, [%4];"
                 : "=r"(r[0]), "=r"(r[1]), "=r"(r[2]), "=r"(r[3]) : "r"(addr));
}
__device__ __forceinline__ void mma_bf16(float* c, const uint32_t* a,
                                         uint32_t b0, uint32_t b1) {
    asm volatile(
        "mma.sync.aligned.m16n8k16.row.col.f32.bf16.bf16.f32 "
        "{%0,%1,%2,%3}, {%4,%5,%6,%7}, {%8,%9}, {%0,%1,%2,%3};"
        : "+f"(c[0]), "+f"(c[1]), "+f"(c[2]), "+f"(c[3])
        : "r"(a[0]), "r"(a[1]), "r"(a[2]), "r"(a[3]), "r"(b0), "r"(b1));
}
__device__ __forceinline__ float fast_tanh(float x) {
    float y; asm("tanh.approx.f32 %0, %1;" : "=f"(y) : "f"(x)); return y;
}
#define CP16(dst, src) \
    asm volatile("cp.async.cg.shared.global [%0], [%1], 16;" :: "r"(dst), "l"(src))
#define CP_COMMIT() asm volatile("cp.async.commit_group;" ::: "memory")
#define CP_WAIT(N)  asm volatile("cp.async.wait_group %0;" :: "n"(N) : "memory")

// SMEM tile: 128 rows x 64 bf16 (128B) padded to 144 B/row (conflict-free ldmatrix)
#define SROW2 144
#define TILE2 (128*SROW2)      // 18432 bytes
#define NCH   12               // 768 / 64

// Shared 128x128x64 chunk MMA with B-fragment ping-pong prefetch.
// Uses: acc[2][8][4], wm, wn, lane_off from enclosing scope.
#define CHUNK_MMA(AsX, BsX) do { \
    _Pragma("unroll") \
    for (int ks = 0; ks < 4; ks++) { \
        uint32_t a0[4], a1[4], bmA[4], bmB[4]; \
        ldsm_x4(a0,  (AsX) + (uint32_t)(wm * 32)      * SROW2 + ks * 32 + lane_off); \
        ldsm_x4(a1,  (AsX) + (uint32_t)(wm * 32 + 16) * SROW2 + ks * 32 + lane_off); \
        ldsm_x4(bmA, (BsX) + (uint32_t)(wn * 64)      * SROW2 + ks * 32 + lane_off); \
        _Pragma("unroll") \
        for (int np = 0; np < 4; np++) { \
            uint32_t* bc = (np & 1) ? bmB : bmA; \
            uint32_t* bn_ = (np & 1) ? bmA : bmB; \
            if (np < 3) \
                ldsm_x4(bn_, (BsX) + (uint32_t)(wn * 64 + (np + 1) * 16) * SROW2 \
                               + ks * 32 + lane_off); \
            mma_bf16(acc[0][np*2],   a0, bc[0], bc[2]); \
            mma_bf16(acc[0][np*2+1], a0, bc[1], bc[3]); \
            mma_bf16(acc[1][np*2],   a1, bc[0], bc[2]); \
            mma_bf16(acc[1][np*2+1], a1, bc[1], bc[3]); \
        } \
    } \
} while (0)

// ---------------------------------------------------------------------------
// small elementwise kernels (merged: blockIdx.z selects operand pair)
// ---------------------------------------------------------------------------
__global__ void convert_bf16_2(const float* __restrict__ x1, const float* __restrict__ x2,
                               __nv_bfloat16* __restrict__ y1, __nv_bfloat16* __restrict__ y2)
{
    const float* x = blockIdx.z ? x2 : x1;
    __nv_bfloat16* y = blockIdx.z ? y2 : y1;
    const size_t i = ((size_t)blockIdx.x * blockDim.x + threadIdx.x) * 8;
    float4 v0 = *(const float4*)(x + i);
    float4 v1 = *(const float4*)(x + i + 4);
    __nv_bfloat162 a = __floats2bfloat162_rn(v0.x, v0.y);
    __nv_bfloat162 b = __floats2bfloat162_rn(v0.z, v0.w);
    __nv_bfloat162 c = __floats2bfloat162_rn(v1.x, v1.y);
    __nv_bfloat162 d = __floats2bfloat162_rn(v1.z, v1.w);
    uint4 st; st.x = *(uint32_t*)&a; st.y = *(uint32_t*)&b;
    st.z = *(uint32_t*)&c; st.w = *(uint32_t*)&d;
    *(uint4*)(y + i) = st;
}

__global__ void transpose_bf16_2(const float* __restrict__ W1, const float* __restrict__ W2,
                                 __nv_bfloat16* __restrict__ T1, __nv_bfloat16* __restrict__ T2)
{
    const float* W = blockIdx.z ? W2 : W1;
    __nv_bfloat16* Wt = blockIdx.z ? T2 : T1;
    __shared__ float t[32][33];
    int tx = threadIdx.x, ty = threadIdx.y;
    int bk = blockIdx.y * 32, bn = blockIdx.x * 32;
#pragma unroll
    for (int j = 0; j < 4; j++)
        t[ty + j * 8][tx] = W[(size_t)(bk + ty + j * 8) * DIM + bn + tx];
    __syncthreads();
#pragma unroll
    for (int j = 0; j < 4; j++)
        Wt[(size_t)(bn + ty + j * 8) * DIM + bk + tx] = __float2bfloat16(t[tx][ty + j * 8]);
}

__global__ void finalize(const float* __restrict__ n0, const float* __restrict__ n1,
                         const float* __restrict__ d0, const float* __restrict__ d1,
                         float* __restrict__ out)
{
    const int i = blockIdx.x * blockDim.x + threadIdx.x;
    out[i] = (n0[i] + n1[i]) / (d0[i] + d1[i] + 1e-7f);
}

// ---------------------------------------------------------------------------
// Phase 1 (merged Q & K via blockIdx.z):
// Out[m,n] = bf16( sum_k A_bf16[m,k]*Wt_bf16[n,k] + bias[n] )
// CTA 128x128, K chunks of 64, cp.async 3-stage for BOTH A and B.
// 8 warps (4m x 2n), warp tile 32x64 (mma m16n8k16).
// SMEM layout: A0,A1,A2 | B0,B1,B2 | bias
// ---------------------------------------------------------------------------
#define P1_SMEM (6*TILE2 + 512)

__global__ void __launch_bounds__(256, 2)
gemm_bias_mma(const __nv_bfloat16* __restrict__ A1, const __nv_bfloat16* __restrict__ A2,
              const __nv_bfloat16* __restrict__ B1, const __nv_bfloat16* __restrict__ B2,
              const float* __restrict__ bias1, const float* __restrict__ bias2,
              __nv_bfloat16* __restrict__ O1, __nv_bfloat16* __restrict__ O2)
{
    extern __shared__ __align__(16) char smem[];
    const uint32_t sb = smem_u32(smem);
    const int tid = threadIdx.x, lane = tid & 31, wid = tid >> 5;
    const int wm = wid >> 1, wn = wid & 1;
    const int n0 = blockIdx.x * 128, m0 = blockIdx.y * 128;
    const int z = blockIdx.z;

    const __nv_bfloat16* A  = z ? A2 : A1;
    const __nv_bfloat16* Bt = z ? B2 : B1;
    const float* bias       = z ? bias2 : bias1;
    __nv_bfloat16* Out      = z ? O2 : O1;

    float* bias_s = (float*)(smem + 6*TILE2);
    if (tid < 128) bias_s[tid] = bias[n0 + tid];

    const __nv_bfloat16* Ag = A  + (size_t)m0 * DIM;
    const __nv_bfloat16* Bg = Bt + (size_t)n0 * DIM;

    const int br = tid >> 3, bsg = tid & 7;   // 32 rows/pass, 8 segs of 16B
    const uint32_t lane_off = (uint32_t)(lane & 15) * SROW2 + (uint32_t)(lane >> 4) * 16;

    float acc[2][8][4];
#pragma unroll
    for (int i = 0; i < 2; i++)
#pragma unroll
        for (int j = 0; j < 8; j++)
#pragma unroll
            for (int q = 0; q < 4; q++) acc[i][j][q] = 0.f;

#define GEMM_ISSUE(cc) do { \
        const int _bf = (cc) % 3; \
        const uint32_t _da = sb + _bf * TILE2; \
        const uint32_t _db = sb + 3*TILE2 + _bf * TILE2; \
        _Pragma("unroll") \
        for (int _p = 0; _p < 4; _p++) { \
            const int _r = br + _p * 32; \
            CP16(_da + _r * SROW2 + bsg * 16, \
                 (const char*)(Ag + (size_t)_r * DIM + (cc) * 64 + bsg * 8)); \
            CP16(_db + _r * SROW2 + bsg * 16, \
                 (const char*)(Bg + (size_t)_r * DIM + (cc) * 64 + bsg * 8)); \
        } \
        CP_COMMIT(); \
    } while (0)

    GEMM_ISSUE(0);
    GEMM_ISSUE(1);

    for (int c = 0; c < NCH; c++) {
        if (c < NCH - 1) CP_WAIT(1); else CP_WAIT(0);
        __syncthreads();
        if (c + 2 < NCH) GEMM_ISSUE(c + 2);

        const uint32_t As = sb + (c % 3) * TILE2;
        const uint32_t Bs = sb + 3*TILE2 + (c % 3) * TILE2;
        CHUNK_MMA(As, Bs);
    }
#undef GEMM_ISSUE

    // epilogue: + bias, bf16 store
#pragma unroll
    for (int mt = 0; mt < 2; mt++) {
        const int m = m0 + wm * 32 + mt * 16 + (lane >> 2);
#pragma unroll
        for (int nt = 0; nt < 8; nt++) {
            const int nl = wn * 64 + nt * 8 + (lane & 3) * 2;
            const float b0 = bias_s[nl], b1 = bias_s[nl + 1];
            __nv_bfloat162 p0 = __floats2bfloat162_rn(acc[mt][nt][0] + b0, acc[mt][nt][1] + b1);
            __nv_bfloat162 p1 = __floats2bfloat162_rn(acc[mt][nt][2] + b0, acc[mt][nt][3] + b1);
            *(__nv_bfloat162*)(Out + (size_t)m       * DIM + n0 + nl) = p0;
            *(__nv_bfloat162*)(Out + (size_t)(m + 8) * DIM + n0 + nl) = p1;
        }
    }
}

// ---------------------------------------------------------------------------
// Phase 2: per (t-block 128, batch, s-half 1024): 8 s-tiles of 128.
// Flattened 96-chunk cp.async 3-stage pipeline (Q & K per chunk, one group).
// Per tile epilogue: e=exp(tanh(qk)); num[t]+=e*qk; den[t]+=e.
// Partial results per s-half -> g_num[sh], g_den[sh] (no global atomics).
// SMEM layout: Q0,Q1,Q2 | K0,K1,K2 | num(512) den(512)
// ---------------------------------------------------------------------------
#define P2_SMEM (6*TILE2 + 1024)
#define GTOT (8*NCH)   // 96

__global__ void __launch_bounds__(256, 2)
attn_mma(const __nv_bfloat16* __restrict__ Q, const __nv_bfloat16* __restrict__ K,
         float* __restrict__ gnum0, float* __restrict__ gnum1,
         float* __restrict__ gden0, float* __restrict__ gden1)
{
    extern __shared__ __align__(16) char smem[];
    const uint32_t sb = smem_u32(smem);
    float* num_sh = (float*)(smem + 6*TILE2);
    float* den_sh = num_sh + 128;

    const int tid = threadIdx.x, lane = tid & 31, wid = tid >> 5;
    const int wm = wid >> 1, wn = wid & 1;
    const int t0 = blockIdx.x * 128, b = blockIdx.y, sh = blockIdx.z;

    if (tid < 128) { num_sh[tid] = 0.f; den_sh[tid] = 0.f; }

    const __nv_bfloat16* Kg    = K + ((size_t)b * SEQ + t0) * DIM;
    const __nv_bfloat16* Qbase = Q + ((size_t)b * SEQ + sh * 1024) * DIM;

    const int br = tid >> 3, bsg = tid & 7;
    const uint32_t lane_off = (uint32_t)(lane & 15) * SROW2 + (uint32_t)(lane >> 4) * 16;

    float acc[2][8][4];
#pragma unroll
    for (int i = 0; i < 2; i++)
#pragma unroll
        for (int j = 0; j < 8; j++)
#pragma unroll
            for (int q = 0; q < 4; q++) acc[i][j][q] = 0.f;

#define ATTN_ISSUE(gg) do { \
        const int _st = (gg) / NCH, _cc = (gg) % NCH, _bf = (gg) % 3; \
        const __nv_bfloat16* _Qp = Qbase + (size_t)(_st * 128) * DIM + _cc * 64; \
        const __nv_bfloat16* _Kp = Kg + _cc * 64; \
        const uint32_t _dq = sb + _bf * TILE2; \
        const uint32_t _dk = sb + 3*TILE2 + _bf * TILE2; \
        _Pragma("unroll") \
        for (int _p = 0; _p < 4; _p++) { \
            const int _r = br + _p * 32; \
            CP16(_dq + _r * SROW2 + bsg * 16, (const char*)(_Qp + (size_t)_r * DIM + bsg * 8)); \
            CP16(_dk + _r * SROW2 + bsg * 16, (const char*)(_Kp + (size_t)_r * DIM + bsg * 8)); \
        } \
        CP_COMMIT(); \
    } while (0)

    ATTN_ISSUE(0);
    ATTN_ISSUE(1);

    for (int g = 0; g < GTOT; g++) {
        if (g < GTOT - 1) CP_WAIT(1); else CP_WAIT(0);
        __syncthreads();
        if (g + 2 < GTOT) ATTN_ISSUE(g + 2);

        const uint32_t As = sb + (g % 3) * TILE2;
        const uint32_t Bs = sb + 3*TILE2 + (g % 3) * TILE2;
        CHUNK_MMA(As, Bs);

        if ((g % NCH) == NCH - 1) {
            // s-tile complete: epilogue, reduce over s into num/den per t
#pragma unroll
            for (int nt = 0; nt < 8; nt++) {
                float vn0 = 0.f, vn1 = 0.f, vd0 = 0.f, vd1 = 0.f;
#pragma unroll
                for (int mt = 0; mt < 2; mt++) {
                    const float q0 = acc[mt][nt][0], q1 = acc[mt][nt][1];
                    const float q2 = acc[mt][nt][2], q3 = acc[mt][nt][3];
                    const float e0 = __expf(fast_tanh(q0));
                    const float e1 = __expf(fast_tanh(q1));
                    const float e2 = __expf(fast_tanh(q2));
                    const float e3 = __expf(fast_tanh(q3));
                    vn0 += e0 * q0 + e2 * q2;  vd0 += e0 + e2;
                    vn1 += e1 * q1 + e3 * q3;  vd1 += e1 + e3;
                }
#pragma unroll
                for (int o = 4; o <= 16; o <<= 1) {
                    vn0 += __shfl_xor_sync(0xFFFFFFFFu, vn0, o);
                    vn1 += __shfl_xor_sync(0xFFFFFFFFu, vn1, o);
                    vd0 += __shfl_xor_sync(0xFFFFFFFFu, vd0, o);
                    vd1 += __shfl_xor_sync(0xFFFFFFFFu, vd1, o);
                }
                if (lane < 4) {
                    const int col = wn * 64 + nt * 8 + lane * 2;
                    atomicAdd(&num_sh[col],     vn0);
                    atomicAdd(&num_sh[col + 1], vn1);
                    atomicAdd(&den_sh[col],     vd0);
                    atomicAdd(&den_sh[col + 1], vd1);
                }
            }
#pragma unroll
            for (int i = 0; i < 2; i++)
#pragma unroll
                for (int j = 0; j < 8; j++)
#pragma unroll
                    for (int q = 0; q < 4; q++) acc[i][j][q] = 0.f;
        }
    }
    __syncthreads();
    if (tid < 128) {
        float* gn = sh ? gnum1 : gnum0;
        float* gd = sh ? gden1 : gden0;
        gn[(size_t)b * SEQ + t0 + tid] = num_sh[tid];
        gd[(size_t)b * SEQ + t0 + tid] = den_sh[tid];
    }
#undef ATTN_ISSUE
}

// ---------------------------------------------------------------------------
extern "C" void kernel_launch(void* const* d_in, const int* in_sizes, int n_in,
                              void* d_out, int out_size)
{
    const float* x1 = (const float*)d_in[0];
    const float* x2 = (const float*)d_in[1];
    const float* Wq = (const float*)d_in[2];
    const float* bq = (const float*)d_in[3];
    const float* Wk = (const float*)d_in[4];
    const float* bk = (const float*)d_in[5];
    float* out = (float*)d_out;

    __nv_bfloat16 *X1b, *X2b, *Qp, *Kp, *Wqt, *Wkt;
    float *gnum, *gden;
    cudaGetSymbolAddress((void**)&X1b, g_X1b);
    cudaGetSymbolAddress((void**)&X2b, g_X2b);
    cudaGetSymbolAddress((void**)&Qp,  g_Q);
    cudaGetSymbolAddress((void**)&Kp,  g_K);
    cudaGetSymbolAddress((void**)&Wqt, g_Wqt);
    cudaGetSymbolAddress((void**)&Wkt, g_Wkt);
    cudaGetSymbolAddress((void**)&gnum, g_num);
    cudaGetSymbolAddress((void**)&gden, g_den);
    float* gnum1 = gnum + BATCH*SEQ;
    float* gden1 = gden + BATCH*SEQ;

    cudaFuncSetAttribute(gemm_bias_mma, cudaFuncAttributeMaxDynamicSharedMemorySize, P1_SMEM);
    cudaFuncSetAttribute(attn_mma,      cudaFuncAttributeMaxDynamicSharedMemorySize, P2_SMEM);

    const int nconv = (int)(((size_t)MTOT * DIM / 8) / 256);   // 6144 blocks
    convert_bf16_2<<<dim3(nconv, 1, 2), 256>>>(x1, x2, X1b, X2b);

    dim3 tgrid(DIM / 32, DIM / 32, 2);
    transpose_bf16_2<<<tgrid, dim3(32, 8)>>>(Wq, Wk, Wqt, Wkt);

    dim3 ggrid(DIM / 128, MTOT / 128, 2);   // (6, 128, 2) = 1536 CTAs
    gemm_bias_mma<<<ggrid, 256, P1_SMEM>>>(X1b, X2b, Wqt, Wkt, bq, bk, Qp, Kp);

    dim3 agrid(SEQ / 128, BATCH, 2);        // (16, 8, 2)
    attn_mma<<<agrid, 256, P2_SMEM>>>(Qp, Kp, gnum, gnum1, gden, gden1);

    finalize<<<BATCH*SEQ/256, 256>>>(gnum, gnum1, gden, gden1, out);
}